// round 10
// baseline (speedup 1.0000x reference)
#include <cuda_runtime.h>
#include <cuda_fp16.h>
#include <cstdint>

#define N_NODES 50000
#define N_EDGES 800000
#define D 64
#define CAP 64
#define HALFN (N_NODES / 2)   // 25000

// -------- device scratch (zero-initialized; no allocations allowed) --------
__device__ __half   g_node16[N_NODES * D];     // fp16 (embed * outdeg)   6.4 MB
__device__ float    g_acc[N_NODES * D];        // fp32 x = embed+N_h*ind 12.8 MB
__device__ int      g_cnt[N_NODES];            // bucket cursors
__device__ uint32_t g_edges[N_NODES * CAP];    // (src<<16)|fp16(ew)     12.8 MB
__device__ uint4    g_ovf[4096];               // overflow (src,dst,w32,-)
__device__ int      g_ovf_cnt;

// ---------------------------------------------------------------------------
// 1. fused prep + scatter, 2 edges / 8 prep-elems per thread (400K threads).
//    (Byte-identical hot path to R5/R6 — measured invariant at ~18.2us.)
// ---------------------------------------------------------------------------
__global__ void prep_scatter_kernel(const float* __restrict__ embed,
                                    const int* __restrict__ src,
                                    const int* __restrict__ dst,
                                    const float* __restrict__ ew,
                                    const float* __restrict__ outdeg) {
    int t = blockIdx.x * blockDim.x + threadIdx.x;
    if (t >= N_EDGES / 2) return;

    // ---- prep: 8 consecutive elems (one outdeg row covers them) ----
    {
        float4 v0 = __ldg((const float4*)embed + 2 * t);
        float4 v1 = __ldg((const float4*)embed + 2 * t + 1);
        float od = __ldg(&outdeg[t >> 3]);
        __half2 h0 = __floats2half2_rn(v0.x * od, v0.y * od);
        __half2 h1 = __floats2half2_rn(v0.z * od, v0.w * od);
        __half2 h2 = __floats2half2_rn(v1.x * od, v1.y * od);
        __half2 h3 = __floats2half2_rn(v1.z * od, v1.w * od);
        uint4 pk;
        pk.x = *reinterpret_cast<uint32_t*>(&h0);
        pk.y = *reinterpret_cast<uint32_t*>(&h1);
        pk.z = *reinterpret_cast<uint32_t*>(&h2);
        pk.w = *reinterpret_cast<uint32_t*>(&h3);
        ((uint4*)g_node16)[t] = pk;
    }

    // ---- scatter 2 edges (independent chains) ----
    {
        int2   s2 = ((const int2*)src)[t];
        int2   d2 = ((const int2*)dst)[t];
        float2 w2 = ((const float2*)ew)[t];

        uint32_t rec0 = ((uint32_t)s2.x << 16) |
                        (uint32_t)__half_as_ushort(__float2half_rn(w2.x));
        uint32_t rec1 = ((uint32_t)s2.y << 16) |
                        (uint32_t)__half_as_ushort(__float2half_rn(w2.y));

        int pos0 = atomicAdd(&g_cnt[d2.x], 1);
        int pos1 = atomicAdd(&g_cnt[d2.y], 1);

        if (pos0 < CAP) {
            g_edges[d2.x * CAP + pos0] = rec0;
        } else {
            int op = atomicAdd(&g_ovf_cnt, 1);
            if (op < 4096)
                g_ovf[op] = make_uint4((unsigned)s2.x, (unsigned)d2.x,
                                       __float_as_uint(w2.x), 0u);
        }
        if (pos1 < CAP) {
            g_edges[d2.y * CAP + pos1] = rec1;
        } else {
            int op = atomicAdd(&g_ovf_cnt, 1);
            if (op < 4096)
                g_ovf[op] = make_uint4((unsigned)s2.y, (unsigned)d2.y,
                                       __float_as_uint(w2.y), 0u);
        }
    }
}

// ---------------------------------------------------------------------------
// 2. accumulate: 8 lanes per group; each group owns TWO nodes (g, g+25000),
//    record loads and gathers interleaved -> ~32 in-flight loads per group.
//    fp32 accumulation; writes x = embed + N_h*indeg (fp32) to g_acc.
//    Self-resets g_cnt.
// ---------------------------------------------------------------------------
__device__ __forceinline__ void gather_fma(uint32_t rec, int c,
                                           float2& a0, float2& a1,
                                           float2& a2, float2& a3) {
    float w = __half2float(__ushort_as_half((unsigned short)(rec & 0xFFFFu)));
    uint4 hv = __ldg((const uint4*)(g_node16 + (size_t)(rec >> 16) * D) + c);
    float2 f0 = __half22float2(*(__half2*)&hv.x);
    float2 f1 = __half22float2(*(__half2*)&hv.y);
    float2 f2 = __half22float2(*(__half2*)&hv.z);
    float2 f3 = __half22float2(*(__half2*)&hv.w);
    a0.x = fmaf(f0.x, w, a0.x); a0.y = fmaf(f0.y, w, a0.y);
    a1.x = fmaf(f1.x, w, a1.x); a1.y = fmaf(f1.y, w, a1.y);
    a2.x = fmaf(f2.x, w, a2.x); a2.y = fmaf(f2.y, w, a2.y);
    a3.x = fmaf(f3.x, w, a3.x); a3.y = fmaf(f3.y, w, a3.y);
}

__device__ __forceinline__ void store_x(int n, int c, float ind,
                                        const float* __restrict__ embed,
                                        const float2& a0, const float2& a1,
                                        const float2& a2, const float2& a3) {
    float4 e0 = __ldg((const float4*)(embed + (size_t)n * D) + 2 * c);
    float4 e1 = __ldg((const float4*)(embed + (size_t)n * D) + 2 * c + 1);
    float* op = g_acc + (size_t)n * D + c * 8;
    ((float4*)op)[0] = make_float4(e0.x + a0.x * ind, e0.y + a0.y * ind,
                                   e0.z + a1.x * ind, e0.w + a1.y * ind);
    ((float4*)op)[1] = make_float4(e1.x + a2.x * ind, e1.y + a2.y * ind,
                                   e1.z + a3.x * ind, e1.w + a3.y * ind);
}

__global__ void accum_kernel(const float* __restrict__ embed,
                             const float* __restrict__ indeg) {
    int gid = blockIdx.x * blockDim.x + threadIdx.x;
    int g = gid >> 3;
    if (g >= HALFN) return;
    int c = gid & 7;
    unsigned gmask = 0xFFu << (threadIdx.x & 24);  // this 8-lane group

    int n0 = g;
    int n1 = g + HALFN;

    int cr0 = g_cnt[n0];
    int cr1 = g_cnt[n1];
    int cnt0 = cr0 < CAP ? cr0 : CAP;
    int cnt1 = cr1 < CAP ? cr1 : CAP;
    const uint32_t* bk0 = g_edges + (size_t)n0 * CAP;
    const uint32_t* bk1 = g_edges + (size_t)n1 * CAP;

    __syncwarp();
    if (c == 0) { g_cnt[n0] = 0; g_cnt[n1] = 0; }   // reset for next replay

    float2 p0 = make_float2(0.f, 0.f), p1 = p0, p2 = p0, p3 = p0;  // node0
    float2 q0 = make_float2(0.f, 0.f), q1 = q0, q2 = q0, q3 = q0;  // node1

    int cmax = cnt0 > cnt1 ? cnt0 : cnt1;
    for (int base = 0; base < cmax; base += 16) {
        // preload records for both nodes (4 independent LDGs)
        uint32_t ra0 = 0, ra1 = 0, rb0 = 0, rb1 = 0;
        if (base + c < cnt0)     ra0 = __ldg(&bk0[base + c]);
        if (base + 8 + c < cnt0) ra1 = __ldg(&bk0[base + 8 + c]);
        if (base + c < cnt1)     rb0 = __ldg(&bk1[base + c]);
        if (base + 8 + c < cnt1) rb1 = __ldg(&bk1[base + 8 + c]);
        int rem0 = cnt0 - base;
        int rem1 = cnt1 - base;
#pragma unroll
        for (int i = 0; i < 16; i++) {
            if (i < rem0) {
                uint32_t rec = __shfl_sync(gmask, (i < 8) ? ra0 : ra1, i & 7, 8);
                gather_fma(rec, c, p0, p1, p2, p3);
            }
            if (i < rem1) {
                uint32_t rec = __shfl_sync(gmask, (i < 8) ? rb0 : rb1, i & 7, 8);
                gather_fma(rec, c, q0, q1, q2, q3);
            }
        }
    }

    // overflow fallback (effectively never taken)
    if (cr0 > CAP || cr1 > CAP) {
        int m = g_ovf_cnt; if (m > 4096) m = 4096;
        for (int i = 0; i < m; i++) {
            uint4 rec = g_ovf[i];
            uint32_t r = (rec.x << 16);   // src in high bits; weight via fp32
            float w = __uint_as_float(rec.z);
            if ((int)rec.y == n0) {
                uint4 hv = __ldg((const uint4*)(g_node16 + (size_t)rec.x * D) + c);
                float2 f0 = __half22float2(*(__half2*)&hv.x);
                float2 f1 = __half22float2(*(__half2*)&hv.y);
                float2 f2 = __half22float2(*(__half2*)&hv.z);
                float2 f3 = __half22float2(*(__half2*)&hv.w);
                p0.x = fmaf(f0.x, w, p0.x); p0.y = fmaf(f0.y, w, p0.y);
                p1.x = fmaf(f1.x, w, p1.x); p1.y = fmaf(f1.y, w, p1.y);
                p2.x = fmaf(f2.x, w, p2.x); p2.y = fmaf(f2.y, w, p2.y);
                p3.x = fmaf(f3.x, w, p3.x); p3.y = fmaf(f3.y, w, p3.y);
            }
            if ((int)rec.y == n1) {
                uint4 hv = __ldg((const uint4*)(g_node16 + (size_t)rec.x * D) + c);
                float2 f0 = __half22float2(*(__half2*)&hv.x);
                float2 f1 = __half22float2(*(__half2*)&hv.y);
                float2 f2 = __half22float2(*(__half2*)&hv.z);
                float2 f3 = __half22float2(*(__half2*)&hv.w);
                q0.x = fmaf(f0.x, w, q0.x); q0.y = fmaf(f0.y, w, q0.y);
                q1.x = fmaf(f1.x, w, q1.x); q1.y = fmaf(f1.y, w, q1.y);
                q2.x = fmaf(f2.x, w, q2.x); q2.y = fmaf(f2.y, w, q2.y);
                q3.x = fmaf(f3.x, w, q3.x); q3.y = fmaf(f3.y, w, q3.y);
            }
            (void)r;
        }
    }

    store_x(n0, c, __ldg(&indeg[n0]), embed, p0, p1, p2, p3);
    store_x(n1, c, __ldg(&indeg[n1]), embed, q0, q1, q2, q3);
}

// ---------------------------------------------------------------------------
// 3. out = LeakyReLU(g_acc @ W^T + b)   [g_acc = embed + N_h*indeg, fp32]
//    Tiled GEMM: 128 rows x 64 cols per block, 128 threads, 8x8/thread,
//    packed fma.rn.f32x2.  (Exactly the R5 version: proven.)
// ---------------------------------------------------------------------------
typedef unsigned long long ull;
__device__ __forceinline__ ull fma_f2(ull a, ull b, ull c) {
    ull d;
    asm("fma.rn.f32x2 %0, %1, %2, %3;" : "=l"(d) : "l"(a), "l"(b), "l"(c));
    return d;
}
__device__ __forceinline__ ull pack_f2(float lo, float hi) {
    ull r;
    asm("mov.b64 %0, {%1, %2};" : "=l"(r) : "f"(lo), "f"(hi));
    return r;
}
__device__ __forceinline__ void unpack_f2(ull v, float& lo, float& hi) {
    asm("mov.b64 {%0, %1}, %2;" : "=f"(lo), "=f"(hi) : "l"(v));
}

#define OB_ROWS 128

__global__ void __launch_bounds__(128) out_kernel(const float* __restrict__ W,
                                                  const float* __restrict__ b,
                                                  float* __restrict__ out) {
    __shared__ float xs[OB_ROWS][D + 1];
    __shared__ float Wt[D][D];
    __shared__ float bs[D];

    int tid = threadIdx.x;
    if (blockIdx.x == 0 && tid == 0) g_ovf_cnt = 0;   // reset for next replay

    for (int i = tid; i < D * D; i += 128) {
        int j = i >> 6, k = i & 63;
        Wt[k][j] = W[i];
    }
    if (tid < D) bs[tid] = b[tid];

    int row0 = blockIdx.x * OB_ROWS;
    for (int i = tid; i < OB_ROWS * (D / 4); i += 128) {
        int r = i >> 4, q = i & 15;
        int gr = row0 + r;
        int grc = gr < N_NODES ? gr : N_NODES - 1;
        float4 a = *((const float4*)(g_acc + (size_t)grc * D) + q);
        xs[r][q * 4 + 0] = a.x;
        xs[r][q * 4 + 1] = a.y;
        xs[r][q * 4 + 2] = a.z;
        xs[r][q * 4 + 3] = a.w;
    }
    __syncthreads();

    int tx = tid & 7;        // col octet
    int ty = tid >> 3;       // row octet

    ull acc[8][4];
    {
        ulonglong2 b01 = *(const ulonglong2*)&bs[tx * 8];
        ulonglong2 b23 = *(const ulonglong2*)&bs[tx * 8 + 4];
#pragma unroll
        for (int rr = 0; rr < 8; rr++) {
            acc[rr][0] = b01.x; acc[rr][1] = b01.y;
            acc[rr][2] = b23.x; acc[rr][3] = b23.y;
        }
    }

#pragma unroll 4
    for (int k = 0; k < D; k++) {
        ulonglong2 w01 = *(const ulonglong2*)&Wt[k][tx * 8];
        ulonglong2 w23 = *(const ulonglong2*)&Wt[k][tx * 8 + 4];
#pragma unroll
        for (int rr = 0; rr < 8; rr++) {
            float xv = xs[ty * 8 + rr][k];
            ull xp = pack_f2(xv, xv);
            acc[rr][0] = fma_f2(xp, w01.x, acc[rr][0]);
            acc[rr][1] = fma_f2(xp, w01.y, acc[rr][1]);
            acc[rr][2] = fma_f2(xp, w23.x, acc[rr][2]);
            acc[rr][3] = fma_f2(xp, w23.y, acc[rr][3]);
        }
    }

#pragma unroll
    for (int rr = 0; rr < 8; rr++) {
        int gr = row0 + ty * 8 + rr;
        if (gr < N_NODES) {
            float o[8];
#pragma unroll
            for (int p = 0; p < 4; p++) unpack_f2(acc[rr][p], o[2 * p], o[2 * p + 1]);
#pragma unroll
            for (int q = 0; q < 8; q++) o[q] = o[q] > 0.f ? o[q] : 0.01f * o[q];
            float* dst = out + (size_t)gr * D + tx * 8;
            ((float4*)dst)[0] = make_float4(o[0], o[1], o[2], o[3]);
            ((float4*)dst)[1] = make_float4(o[4], o[5], o[6], o[7]);
        }
    }
}

// ---------------------------------------------------------------------------
// kernel_launch — 3 launches
// ---------------------------------------------------------------------------
extern "C" void kernel_launch(void* const* d_in, const int* in_sizes, int n_in,
                              void* d_out, int out_size) {
    const float* embed  = (const float*)d_in[0];
    const int*   src    = (const int*)d_in[1];
    const int*   dst    = (const int*)d_in[2];
    const float* ew     = (const float*)d_in[3];
    const float* outdeg = (const float*)d_in[4];
    const float* indeg  = (const float*)d_in[5];
    const float* W      = (const float*)d_in[6];
    const float* b      = (const float*)d_in[7];
    float* out = (float*)d_out;

    {   // 1. fused fp16 prep + bucket scatter (2 edges/thread)
        int threads = 256;
        int blocks = (N_EDGES / 2 + threads - 1) / threads;   // 1563
        prep_scatter_kernel<<<blocks, threads>>>(embed, src, dst, ew, outdeg);
    }
    {   // 2. gather-accumulate: 8 lanes/group, 2 nodes/group (interleaved)
        int total = HALFN * 8;                                // 200K threads
        int threads = 256;
        int blocks = (total + threads - 1) / threads;         // 782
        accum_kernel<<<blocks, threads>>>(embed, indeg);
    }
    {   // 3. tiled GEMM + LeakyReLU (fp32 x input)
        int blocks = (N_NODES + OB_ROWS - 1) / OB_ROWS;       // 391
        out_kernel<<<blocks, 128>>>(W, b, out);
    }
}

// round 11
// speedup vs baseline: 1.0807x; 1.0807x over previous
#include <cuda_runtime.h>
#include <cuda_fp16.h>
#include <cstdint>

#define N_NODES 50000
#define N_EDGES 800000
#define D 64
#define CAP 48              // P(Poisson(16) >= 49) ~ 1e-11: overflow never fires

// -------- device scratch (zero-initialized; no allocations allowed) --------
__device__ __half   g_node16[N_NODES * D];     // fp16 (embed * outdeg)   6.4 MB
__device__ float    g_acc[N_NODES * D];        // fp32 x = embed+N_h*ind 12.8 MB
__device__ int      g_cnt[N_NODES];            // bucket cursors
__device__ uint32_t g_edges[N_NODES * CAP];    // (src<<16)|fp16(ew)      9.6 MB
__device__ uint4    g_ovf[4096];               // overflow (src,dst,w32,-)
__device__ int      g_ovf_cnt;

// ---------------------------------------------------------------------------
// 1. fused prep + scatter, 2 edges / 8 prep-elems per thread (400K threads).
//    (Byte-identical hot path to the 57.86us R5 kernel.)
// ---------------------------------------------------------------------------
__global__ void prep_scatter_kernel(const float* __restrict__ embed,
                                    const int* __restrict__ src,
                                    const int* __restrict__ dst,
                                    const float* __restrict__ ew,
                                    const float* __restrict__ outdeg) {
    int t = blockIdx.x * blockDim.x + threadIdx.x;
    if (t >= N_EDGES / 2) return;

    // ---- prep: 8 consecutive elems (one outdeg row covers them) ----
    {
        float4 v0 = __ldg((const float4*)embed + 2 * t);
        float4 v1 = __ldg((const float4*)embed + 2 * t + 1);
        float od = __ldg(&outdeg[t >> 3]);
        __half2 h0 = __floats2half2_rn(v0.x * od, v0.y * od);
        __half2 h1 = __floats2half2_rn(v0.z * od, v0.w * od);
        __half2 h2 = __floats2half2_rn(v1.x * od, v1.y * od);
        __half2 h3 = __floats2half2_rn(v1.z * od, v1.w * od);
        uint4 pk;
        pk.x = *reinterpret_cast<uint32_t*>(&h0);
        pk.y = *reinterpret_cast<uint32_t*>(&h1);
        pk.z = *reinterpret_cast<uint32_t*>(&h2);
        pk.w = *reinterpret_cast<uint32_t*>(&h3);
        ((uint4*)g_node16)[t] = pk;
    }

    // ---- scatter 2 edges (independent chains) ----
    {
        int2   s2 = ((const int2*)src)[t];
        int2   d2 = ((const int2*)dst)[t];
        float2 w2 = ((const float2*)ew)[t];

        uint32_t rec0 = ((uint32_t)s2.x << 16) |
                        (uint32_t)__half_as_ushort(__float2half_rn(w2.x));
        uint32_t rec1 = ((uint32_t)s2.y << 16) |
                        (uint32_t)__half_as_ushort(__float2half_rn(w2.y));

        int pos0 = atomicAdd(&g_cnt[d2.x], 1);
        int pos1 = atomicAdd(&g_cnt[d2.y], 1);

        if (pos0 < CAP) {
            g_edges[d2.x * CAP + pos0] = rec0;
        } else {
            int op = atomicAdd(&g_ovf_cnt, 1);
            if (op < 4096)
                g_ovf[op] = make_uint4((unsigned)s2.x, (unsigned)d2.x,
                                       __float_as_uint(w2.x), 0u);
        }
        if (pos1 < CAP) {
            g_edges[d2.y * CAP + pos1] = rec1;
        } else {
            int op = atomicAdd(&g_ovf_cnt, 1);
            if (op < 4096)
                g_ovf[op] = make_uint4((unsigned)s2.y, (unsigned)d2.y,
                                       __float_as_uint(w2.y), 0u);
        }
    }
}

// ---------------------------------------------------------------------------
// 2. accumulate: 8 lanes per node (lane c owns 8 halves = 16B chunk).
//    16-record rounds (records loaded once, shfl-broadcast), fp32 accum.
//    Writes x = embed + N_h*indeg (fp32) into g_acc. Self-resets g_cnt.
//    (Exactly the R5 structure — proven fastest.)
// ---------------------------------------------------------------------------
__global__ void accum_kernel(const float* __restrict__ embed,
                             const float* __restrict__ indeg) {
    int gid = blockIdx.x * blockDim.x + threadIdx.x;
    int n = gid >> 3;
    if (n >= N_NODES) return;
    int c = gid & 7;
    unsigned gmask = 0xFFu << (threadIdx.x & 24);  // this 8-lane group

    int cntr = g_cnt[n];
    int cnt = cntr < CAP ? cntr : CAP;
    const uint32_t* bucket = g_edges + (size_t)n * CAP;

    __syncwarp();
    if (c == 0) g_cnt[n] = 0;   // reset for next replay

    float2 a0 = make_float2(0.f, 0.f), a1 = a0, a2 = a0, a3 = a0;

    for (int base = 0; base < cnt; base += 16) {
        uint32_t r0 = 0, r1 = 0;
        if (base + c < cnt)     r0 = __ldg(&bucket[base + c]);
        if (base + 8 + c < cnt) r1 = __ldg(&bucket[base + 8 + c]);
        int rem = cnt - base;
#pragma unroll
        for (int i = 0; i < 16; i++) {
            if (i < rem) {
                uint32_t rec = __shfl_sync(gmask, (i < 8) ? r0 : r1, i & 7, 8);
                float w = __half2float(__ushort_as_half(
                              (unsigned short)(rec & 0xFFFFu)));
                uint4 hv = __ldg((const uint4*)(g_node16 +
                              (size_t)(rec >> 16) * D) + c);
                float2 f0 = __half22float2(*(__half2*)&hv.x);
                float2 f1 = __half22float2(*(__half2*)&hv.y);
                float2 f2 = __half22float2(*(__half2*)&hv.z);
                float2 f3 = __half22float2(*(__half2*)&hv.w);
                a0.x = fmaf(f0.x, w, a0.x); a0.y = fmaf(f0.y, w, a0.y);
                a1.x = fmaf(f1.x, w, a1.x); a1.y = fmaf(f1.y, w, a1.y);
                a2.x = fmaf(f2.x, w, a2.x); a2.y = fmaf(f2.y, w, a2.y);
                a3.x = fmaf(f3.x, w, a3.x); a3.y = fmaf(f3.y, w, a3.y);
            }
        }
    }

    // overflow fallback (never taken at CAP=48; correctness guard)
    if (cntr > CAP) {
        int m = g_ovf_cnt; if (m > 4096) m = 4096;
        for (int i = 0; i < m; i++) {
            uint4 rec = g_ovf[i];
            if ((int)rec.y == n) {
                float w = __uint_as_float(rec.z);
                uint4 hv = __ldg((const uint4*)(g_node16 +
                              (size_t)rec.x * D) + c);
                float2 f0 = __half22float2(*(__half2*)&hv.x);
                float2 f1 = __half22float2(*(__half2*)&hv.y);
                float2 f2 = __half22float2(*(__half2*)&hv.z);
                float2 f3 = __half22float2(*(__half2*)&hv.w);
                a0.x = fmaf(f0.x, w, a0.x); a0.y = fmaf(f0.y, w, a0.y);
                a1.x = fmaf(f1.x, w, a1.x); a1.y = fmaf(f1.y, w, a1.y);
                a2.x = fmaf(f2.x, w, a2.x); a2.y = fmaf(f2.y, w, a2.y);
                a3.x = fmaf(f3.x, w, a3.x); a3.y = fmaf(f3.y, w, a3.y);
            }
        }
    }

    float ind = __ldg(&indeg[n]);
    float4 e0 = __ldg((const float4*)(embed + (size_t)n * D) + 2 * c);
    float4 e1 = __ldg((const float4*)(embed + (size_t)n * D) + 2 * c + 1);
    float* op = g_acc + (size_t)n * D + c * 8;
    ((float4*)op)[0] = make_float4(e0.x + a0.x * ind, e0.y + a0.y * ind,
                                   e0.z + a1.x * ind, e0.w + a1.y * ind);
    ((float4*)op)[1] = make_float4(e1.x + a2.x * ind, e1.y + a2.y * ind,
                                   e1.z + a3.x * ind, e1.w + a3.y * ind);
}

// ---------------------------------------------------------------------------
// 3. out = LeakyReLU(g_acc @ W^T + b)   [g_acc = embed + N_h*indeg]
//    Tiled GEMM: 128 rows x 64 cols per block, 256 threads, 4x8/thread,
//    packed fma.rn.f32x2. (More warps than R5's 128t for load-phase hiding.)
// ---------------------------------------------------------------------------
typedef unsigned long long ull;
__device__ __forceinline__ ull fma_f2(ull a, ull b, ull c) {
    ull d;
    asm("fma.rn.f32x2 %0, %1, %2, %3;" : "=l"(d) : "l"(a), "l"(b), "l"(c));
    return d;
}
__device__ __forceinline__ ull pack_f2(float lo, float hi) {
    ull r;
    asm("mov.b64 %0, {%1, %2};" : "=l"(r) : "f"(lo), "f"(hi));
    return r;
}
__device__ __forceinline__ void unpack_f2(ull v, float& lo, float& hi) {
    asm("mov.b64 {%0, %1}, %2;" : "=f"(lo), "=f"(hi) : "l"(v));
}

#define OB_ROWS 128

__global__ void __launch_bounds__(256) out_kernel(const float* __restrict__ W,
                                                  const float* __restrict__ b,
                                                  float* __restrict__ out) {
    __shared__ float xs[OB_ROWS][D + 1];
    __shared__ float Wt[D][D];
    __shared__ float bs[D];

    int tid = threadIdx.x;
    if (blockIdx.x == 0 && tid == 0) g_ovf_cnt = 0;   // reset for next replay

    for (int i = tid; i < D * D; i += 256) {
        int j = i >> 6, k = i & 63;
        Wt[k][j] = W[i];
    }
    if (tid < D) bs[tid] = b[tid];

    int row0 = blockIdx.x * OB_ROWS;
    for (int i = tid; i < OB_ROWS * (D / 4); i += 256) {
        int r = i >> 4, q = i & 15;
        int gr = row0 + r;
        int grc = gr < N_NODES ? gr : N_NODES - 1;
        float4 a = *((const float4*)(g_acc + (size_t)grc * D) + q);
        xs[r][q * 4 + 0] = a.x;
        xs[r][q * 4 + 1] = a.y;
        xs[r][q * 4 + 2] = a.z;
        xs[r][q * 4 + 3] = a.w;
    }
    __syncthreads();

    int tx = tid & 7;        // col octet: cols [8tx, 8tx+8)
    int ty = tid >> 3;       // row quad:  rows [4ty, 4ty+4)

    ull acc[4][4];
    {
        ulonglong2 b01 = *(const ulonglong2*)&bs[tx * 8];
        ulonglong2 b23 = *(const ulonglong2*)&bs[tx * 8 + 4];
#pragma unroll
        for (int rr = 0; rr < 4; rr++) {
            acc[rr][0] = b01.x; acc[rr][1] = b01.y;
            acc[rr][2] = b23.x; acc[rr][3] = b23.y;
        }
    }

#pragma unroll 4
    for (int k = 0; k < D; k++) {
        ulonglong2 w01 = *(const ulonglong2*)&Wt[k][tx * 8];
        ulonglong2 w23 = *(const ulonglong2*)&Wt[k][tx * 8 + 4];
#pragma unroll
        for (int rr = 0; rr < 4; rr++) {
            float xv = xs[ty * 4 + rr][k];
            ull xp = pack_f2(xv, xv);
            acc[rr][0] = fma_f2(xp, w01.x, acc[rr][0]);
            acc[rr][1] = fma_f2(xp, w01.y, acc[rr][1]);
            acc[rr][2] = fma_f2(xp, w23.x, acc[rr][2]);
            acc[rr][3] = fma_f2(xp, w23.y, acc[rr][3]);
        }
    }

#pragma unroll
    for (int rr = 0; rr < 4; rr++) {
        int gr = row0 + ty * 4 + rr;
        if (gr < N_NODES) {
            float o[8];
#pragma unroll
            for (int p = 0; p < 4; p++) unpack_f2(acc[rr][p], o[2 * p], o[2 * p + 1]);
#pragma unroll
            for (int q = 0; q < 8; q++) o[q] = o[q] > 0.f ? o[q] : 0.01f * o[q];
            float* dst = out + (size_t)gr * D + tx * 8;
            ((float4*)dst)[0] = make_float4(o[0], o[1], o[2], o[3]);
            ((float4*)dst)[1] = make_float4(o[4], o[5], o[6], o[7]);
        }
    }
}

// ---------------------------------------------------------------------------
// kernel_launch — 3 launches
// ---------------------------------------------------------------------------
extern "C" void kernel_launch(void* const* d_in, const int* in_sizes, int n_in,
                              void* d_out, int out_size) {
    const float* embed  = (const float*)d_in[0];
    const int*   src    = (const int*)d_in[1];
    const int*   dst    = (const int*)d_in[2];
    const float* ew     = (const float*)d_in[3];
    const float* outdeg = (const float*)d_in[4];
    const float* indeg  = (const float*)d_in[5];
    const float* W      = (const float*)d_in[6];
    const float* b      = (const float*)d_in[7];
    float* out = (float*)d_out;

    {   // 1. fused fp16 prep + bucket scatter (2 edges/thread)
        int threads = 256;
        int blocks = (N_EDGES / 2 + threads - 1) / threads;   // 1563
        prep_scatter_kernel<<<blocks, threads>>>(embed, src, dst, ew, outdeg);
    }
    {   // 2. gather-accumulate (8 lanes/node), fp32 x output
        int total = N_NODES * 8;
        int threads = 256;
        int blocks = (total + threads - 1) / threads;         // 1563
        accum_kernel<<<blocks, threads>>>(embed, indeg);
    }
    {   // 3. tiled GEMM + LeakyReLU (256 threads/block)
        int blocks = (N_NODES + OB_ROWS - 1) / OB_ROWS;       // 391
        out_kernel<<<blocks, 256>>>(W, b, out);
    }
}

// round 12
// speedup vs baseline: 1.3200x; 1.2215x over previous
#include <cuda_runtime.h>
#include <cuda_fp16.h>
#include <cstdint>

#define N_NODES 50000
#define N_EDGES 800000
#define D 64
#define CAP 64

// -------- device scratch (zero-initialized; no allocations allowed) --------
__device__ __half   g_node16[N_NODES * D];     // fp16 (embed * outdeg)   6.4 MB
__device__ float    g_acc[N_NODES * D];        // fp32 embed + N_h*indeg 12.8 MB
__device__ int      g_cnt[N_NODES];            // bucket cursors
__device__ uint32_t g_edges[N_NODES * CAP];    // (src<<16)|fp16(ew)     12.8 MB
__device__ uint4    g_ovf[4096];               // overflow (src,dst,w32,-)
__device__ int      g_ovf_cnt;

// ---------------------------------------------------------------------------
// 1. fused prep + scatter, 2 edges / 8 prep-elems per thread (400K threads).
// ---------------------------------------------------------------------------
__global__ void prep_scatter_kernel(const float* __restrict__ embed,
                                    const int* __restrict__ src,
                                    const int* __restrict__ dst,
                                    const float* __restrict__ ew,
                                    const float* __restrict__ outdeg) {
    int t = blockIdx.x * blockDim.x + threadIdx.x;
    if (t >= N_EDGES / 2) return;

    // ---- prep: 8 consecutive elems (one outdeg row covers them) ----
    {
        float4 v0 = __ldg((const float4*)embed + 2 * t);
        float4 v1 = __ldg((const float4*)embed + 2 * t + 1);
        float od = __ldg(&outdeg[t >> 3]);
        __half2 h0 = __floats2half2_rn(v0.x * od, v0.y * od);
        __half2 h1 = __floats2half2_rn(v0.z * od, v0.w * od);
        __half2 h2 = __floats2half2_rn(v1.x * od, v1.y * od);
        __half2 h3 = __floats2half2_rn(v1.z * od, v1.w * od);
        uint4 pk;
        pk.x = *reinterpret_cast<uint32_t*>(&h0);
        pk.y = *reinterpret_cast<uint32_t*>(&h1);
        pk.z = *reinterpret_cast<uint32_t*>(&h2);
        pk.w = *reinterpret_cast<uint32_t*>(&h3);
        ((uint4*)g_node16)[t] = pk;
    }

    // ---- scatter 2 edges (independent chains) ----
    {
        int2   s2 = ((const int2*)src)[t];
        int2   d2 = ((const int2*)dst)[t];
        float2 w2 = ((const float2*)ew)[t];

        uint32_t rec0 = ((uint32_t)s2.x << 16) |
                        (uint32_t)__half_as_ushort(__float2half_rn(w2.x));
        uint32_t rec1 = ((uint32_t)s2.y << 16) |
                        (uint32_t)__half_as_ushort(__float2half_rn(w2.y));

        int pos0 = atomicAdd(&g_cnt[d2.x], 1);
        int pos1 = atomicAdd(&g_cnt[d2.y], 1);

        if (pos0 < CAP) {
            g_edges[d2.x * CAP + pos0] = rec0;
        } else {
            int op = atomicAdd(&g_ovf_cnt, 1);
            if (op < 4096)
                g_ovf[op] = make_uint4((unsigned)s2.x, (unsigned)d2.x,
                                       __float_as_uint(w2.x), 0u);
        }
        if (pos1 < CAP) {
            g_edges[d2.y * CAP + pos1] = rec1;
        } else {
            int op = atomicAdd(&g_ovf_cnt, 1);
            if (op < 4096)
                g_ovf[op] = make_uint4((unsigned)s2.y, (unsigned)d2.y,
                                       __float_as_uint(w2.y), 0u);
        }
    }
}

// ---------------------------------------------------------------------------
// 2. accumulate: 8 lanes per node. 16-record rounds: both record words loaded
//    up-front, then all gathers issue back-to-back (MLP~16, one dep level).
//    Writes embed + N_h*indeg (out_kernel reads one stream). Resets g_cnt.
// ---------------------------------------------------------------------------
__global__ void accum_kernel(const float* __restrict__ embed,
                             const float* __restrict__ indeg) {
    int gid = blockIdx.x * blockDim.x + threadIdx.x;
    int n = gid >> 3;
    if (n >= N_NODES) return;
    int c = gid & 7;
    unsigned gmask = 0xFFu << (threadIdx.x & 24);  // this 8-lane group

    int cntr = g_cnt[n];
    int cnt = cntr < CAP ? cntr : CAP;
    const uint32_t* bucket = g_edges + (size_t)n * CAP;

    float2 a0 = make_float2(0.f, 0.f), a1 = a0, a2 = a0, a3 = a0;

    for (int base = 0; base < cnt; base += 16) {
        uint32_t r0 = 0, r1 = 0;
        if (base + c < cnt)     r0 = __ldg(&bucket[base + c]);
        if (base + 8 + c < cnt) r1 = __ldg(&bucket[base + 8 + c]);
        int rem = cnt - base;
#pragma unroll
        for (int i = 0; i < 16; i++) {
            if (i < rem) {
                uint32_t rec = __shfl_sync(gmask, (i < 8) ? r0 : r1, i & 7, 8);
                float w = __half2float(__ushort_as_half(
                              (unsigned short)(rec & 0xFFFFu)));
                uint4 hv = __ldg((const uint4*)(g_node16 +
                              (size_t)(rec >> 16) * D) + c);
                float2 f0 = __half22float2(*(__half2*)&hv.x);
                float2 f1 = __half22float2(*(__half2*)&hv.y);
                float2 f2 = __half22float2(*(__half2*)&hv.z);
                float2 f3 = __half22float2(*(__half2*)&hv.w);
                a0.x = fmaf(f0.x, w, a0.x); a0.y = fmaf(f0.y, w, a0.y);
                a1.x = fmaf(f1.x, w, a1.x); a1.y = fmaf(f1.y, w, a1.y);
                a2.x = fmaf(f2.x, w, a2.x); a2.y = fmaf(f2.y, w, a2.y);
                a3.x = fmaf(f3.x, w, a3.x); a3.y = fmaf(f3.y, w, a3.y);
            }
        }
    }

    // overflow fallback (effectively never taken)
    if (cntr > CAP) {
        int m = g_ovf_cnt; if (m > 4096) m = 4096;
        for (int i = 0; i < m; i++) {
            uint4 rec = g_ovf[i];
            if ((int)rec.y == n) {
                float w = __uint_as_float(rec.z);
                uint4 hv = __ldg((const uint4*)(g_node16 +
                              (size_t)rec.x * D) + c);
                float2 f0 = __half22float2(*(__half2*)&hv.x);
                float2 f1 = __half22float2(*(__half2*)&hv.y);
                float2 f2 = __half22float2(*(__half2*)&hv.z);
                float2 f3 = __half22float2(*(__half2*)&hv.w);
                a0.x = fmaf(f0.x, w, a0.x); a0.y = fmaf(f0.y, w, a0.y);
                a1.x = fmaf(f1.x, w, a1.x); a1.y = fmaf(f1.y, w, a1.y);
                a2.x = fmaf(f2.x, w, a2.x); a2.y = fmaf(f2.y, w, a2.y);
                a3.x = fmaf(f3.x, w, a3.x); a3.y = fmaf(f3.y, w, a3.y);
            }
        }
    }

    float ind = __ldg(&indeg[n]);
    float4 e0 = __ldg((const float4*)(embed + (size_t)n * D) + 2 * c);
    float4 e1 = __ldg((const float4*)(embed + (size_t)n * D) + 2 * c + 1);
    float* op = g_acc + (size_t)n * D + c * 8;
    ((float4*)op)[0] = make_float4(e0.x + a0.x * ind, e0.y + a0.y * ind,
                                   e0.z + a1.x * ind, e0.w + a1.y * ind);
    ((float4*)op)[1] = make_float4(e1.x + a2.x * ind, e1.y + a2.y * ind,
                                   e1.z + a3.x * ind, e1.w + a3.y * ind);

    if (c == 0) g_cnt[n] = 0;   // reset for next replay
}

// ---------------------------------------------------------------------------
// 3. out = LeakyReLU(g_acc @ W^T + b)   [g_acc = embed + N_h*indeg]
//    Tiled GEMM: 128 rows x 64 cols per block, 128 threads, 8x8/thread,
//    packed fma.rn.f32x2.
// ---------------------------------------------------------------------------
typedef unsigned long long ull;
__device__ __forceinline__ ull fma_f2(ull a, ull b, ull c) {
    ull d;
    asm("fma.rn.f32x2 %0, %1, %2, %3;" : "=l"(d) : "l"(a), "l"(b), "l"(c));
    return d;
}
__device__ __forceinline__ ull pack_f2(float lo, float hi) {
    ull r;
    asm("mov.b64 %0, {%1, %2};" : "=l"(r) : "f"(lo), "f"(hi));
    return r;
}
__device__ __forceinline__ void unpack_f2(ull v, float& lo, float& hi) {
    asm("mov.b64 {%0, %1}, %2;" : "=f"(lo), "=f"(hi) : "l"(v));
}

#define OB_ROWS 128

__global__ void __launch_bounds__(128) out_kernel(const float* __restrict__ W,
                                                  const float* __restrict__ b,
                                                  float* __restrict__ out) {
    __shared__ float xs[OB_ROWS][D + 1];
    __shared__ float Wt[D][D];
    __shared__ float bs[D];

    int tid = threadIdx.x;
    if (blockIdx.x == 0 && tid == 0) g_ovf_cnt = 0;   // reset for next replay

    for (int i = tid; i < D * D; i += 128) {
        int j = i >> 6, k = i & 63;
        Wt[k][j] = W[i];
    }
    if (tid < D) bs[tid] = b[tid];

    int row0 = blockIdx.x * OB_ROWS;
    for (int i = tid; i < OB_ROWS * (D / 4); i += 128) {
        int r = i >> 4, q = i & 15;
        int gr = row0 + r;
        int grc = gr < N_NODES ? gr : N_NODES - 1;
        float4 a = *((const float4*)(g_acc + (size_t)grc * D) + q);
        xs[r][q * 4 + 0] = a.x;
        xs[r][q * 4 + 1] = a.y;
        xs[r][q * 4 + 2] = a.z;
        xs[r][q * 4 + 3] = a.w;
    }
    __syncthreads();

    int tx = tid & 7;        // col octet
    int ty = tid >> 3;       // row octet

    ull acc[8][4];
    {
        ulonglong2 b01 = *(const ulonglong2*)&bs[tx * 8];
        ulonglong2 b23 = *(const ulonglong2*)&bs[tx * 8 + 4];
#pragma unroll
        for (int rr = 0; rr < 8; rr++) {
            acc[rr][0] = b01.x; acc[rr][1] = b01.y;
            acc[rr][2] = b23.x; acc[rr][3] = b23.y;
        }
    }

#pragma unroll 4
    for (int k = 0; k < D; k++) {
        ulonglong2 w01 = *(const ulonglong2*)&Wt[k][tx * 8];
        ulonglong2 w23 = *(const ulonglong2*)&Wt[k][tx * 8 + 4];
#pragma unroll
        for (int rr = 0; rr < 8; rr++) {
            float xv = xs[ty * 8 + rr][k];
            ull xp = pack_f2(xv, xv);
            acc[rr][0] = fma_f2(xp, w01.x, acc[rr][0]);
            acc[rr][1] = fma_f2(xp, w01.y, acc[rr][1]);
            acc[rr][2] = fma_f2(xp, w23.x, acc[rr][2]);
            acc[rr][3] = fma_f2(xp, w23.y, acc[rr][3]);
        }
    }

#pragma unroll
    for (int rr = 0; rr < 8; rr++) {
        int gr = row0 + ty * 8 + rr;
        if (gr < N_NODES) {
            float o[8];
#pragma unroll
            for (int p = 0; p < 4; p++) unpack_f2(acc[rr][p], o[2 * p], o[2 * p + 1]);
#pragma unroll
            for (int q = 0; q < 8; q++) o[q] = o[q] > 0.f ? o[q] : 0.01f * o[q];
            float* dst = out + (size_t)gr * D + tx * 8;
            ((float4*)dst)[0] = make_float4(o[0], o[1], o[2], o[3]);
            ((float4*)dst)[1] = make_float4(o[4], o[5], o[6], o[7]);
        }
    }
}

// ---------------------------------------------------------------------------
// kernel_launch — 3 launches
// ---------------------------------------------------------------------------
extern "C" void kernel_launch(void* const* d_in, const int* in_sizes, int n_in,
                              void* d_out, int out_size) {
    const float* embed  = (const float*)d_in[0];
    const int*   src    = (const int*)d_in[1];
    const int*   dst    = (const int*)d_in[2];
    const float* ew     = (const float*)d_in[3];
    const float* outdeg = (const float*)d_in[4];
    const float* indeg  = (const float*)d_in[5];
    const float* W      = (const float*)d_in[6];
    const float* b      = (const float*)d_in[7];
    float* out = (float*)d_out;

    {   // 1. fused fp16 prep + bucket scatter (2 edges/thread)
        int threads = 256;
        int blocks = (N_EDGES / 2 + threads - 1) / threads;   // 1563
        prep_scatter_kernel<<<blocks, threads>>>(embed, src, dst, ew, outdeg);
    }
    {   // 2. gather-accumulate (8 lanes/node, fused embed add)
        int total = N_NODES * 8;
        int threads = 256;
        int blocks = (total + threads - 1) / threads;         // 1563
        accum_kernel<<<blocks, threads>>>(embed, indeg);
    }
    {   // 3. tiled GEMM + LeakyReLU
        int blocks = (N_NODES + OB_ROWS - 1) / OB_ROWS;       // 391
        out_kernel<<<blocks, 128>>>(W, b, out);
    }
}